// round 6
// baseline (speedup 1.0000x reference)
#include <cuda_runtime.h>
#include <cstdint>

#define BB 64
#define NNA 256
#define EE 20
#define DD 25
#define VW_COLS 45          // ATOMEMB + DFEAT
#define NIV 128             // table intervals over [0,5)
#define H_STEP 0.0390625f   // 5/128, exact in fp32
#define INV_H 25.6f

// scratch (__device__ globals per allocation-free rule)
__device__ float4 g_tab[NIV * EE];     // Hermite coeffs {c0,c1,c2,c3} per (interval,o)
__device__ float  g_rowsum[BB * NNA];
__device__ float  g_v;                 // folded bias constant b2 + W2.b1

// ---------------- fast math ----------------
__device__ __forceinline__ float ex2f(float x) {
    float y; asm("ex2.approx.f32 %0, %1;" : "=f"(y) : "f"(x)); return y;
}
__device__ __forceinline__ float rcpf(float x) {
    float y; asm("rcp.approx.f32 %0, %1;" : "=f"(y) : "f"(x)); return y;
}
__device__ __forceinline__ float tanh_fast(float z) {
    float t = ex2f(z * 2.8853900817779268f);   // 2*log2(e)
    return fmaf(-2.0f, rcpf(t + 1.0f), 1.0f);
}

// ---------------- kernel 0: build Hermite table from Vw ----------------
__global__ void k_build(const float* __restrict__ Vw) {
    int t = blockIdx.x * blockDim.x + threadIdx.x;
    if (t >= NIV * EE) return;
    int o = t % EE, iv = t / EE;
    float x0 = iv * H_STEP, x1 = x0 + H_STEP;

    float f0 = 0.f, d0 = 0.f, f1 = 0.f, d1 = 0.f;
    #pragma unroll
    for (int d = 0; d < DD; d++) {
        float w = Vw[o * VW_COLS + 20 + d];
        float u0 = x0 - 0.2f * d;
        float g0 = expf(-2.0f * u0 * u0);
        f0 = fmaf(w, g0, f0);
        d0 = fmaf(w * (-4.0f * u0), g0, d0);
        float u1 = x1 - 0.2f * d;
        float g1 = expf(-2.0f * u1 * u1);
        f1 = fmaf(w, g1, f1);
        d1 = fmaf(w * (-4.0f * u1), g1, d1);
    }
    float h = H_STEP, h2 = h * h, h3 = h2 * h;
    float c2 = (3.0f * (f1 - f0) - (2.0f * d0 + d1) * h) / h2;
    float c3 = (2.0f * (f0 - f1) + (d0 + d1) * h) / h3;
    g_tab[iv * EE + o] = make_float4(f0, d0, c2, c3);
}

// ---------------- kernel 2: fold scalar bias ----------------
__global__ void k_vconst(const float* __restrict__ W2, const float* __restrict__ b1,
                         const float* __restrict__ b2) {
    if (threadIdx.x == 0) {
        float v = b2[0];
        #pragma unroll
        for (int k = 0; k < 10; k++) v = fmaf(W2[k], b1[k], v);
        g_v = v;
    }
}

// ---------------- kernel 1: main pair loop (one warp per row, 8 rows/block) ----------------
__global__ __launch_bounds__(256) void k_main(const int* __restrict__ z,
                                              const float* __restrict__ dist,
                                              const float* __restrict__ emb,
                                              const float* __restrict__ Vw,
                                              const float* __restrict__ Vb,
                                              const float* __restrict__ W1,
                                              const float* __restrict__ W2) {
    __shared__ float4 tab[NIV * EE];   // 40 KB
    __shared__ float  ws1[EE][EE];     // Vw[o, f] for f<20
    __shared__ float  us[EE];          // u = W2 @ W1

    int tid = threadIdx.x;
    #pragma unroll
    for (int t = tid; t < NIV * EE; t += 256) tab[t] = g_tab[t];
    for (int t = tid; t < EE * EE; t += 256) {
        int o = t / EE, f = t % EE;
        ws1[o][f] = Vw[o * VW_COLS + f];
    }
    if (tid < EE) {
        float s = 0.0f;
        #pragma unroll
        for (int k = 0; k < 10; k++) s = fmaf(W2[k], W1[k * EE + tid], s);
        us[tid] = s;
    }
    __syncthreads();

    int warp = tid >> 5, lane = tid & 31;
    int row = blockIdx.x * 8 + warp;

    int   zi = z[row];
    float mk = (zi != 0) ? 1.0f : 0.0f;

    // acc starts at cfeat; accumulates agg over this lane's j's
    float acc[EE];
    #pragma unroll
    for (int o = 0; o < EE; o++) acc[o] = emb[zi * EE + o] * mk;

    if (mk != 0.0f) {
        // base[o] = Vb[o] + cfeat . Vw[o,:20] — one lane per o, then broadcast
        float myb = 0.0f;
        if (lane < EE) {
            myb = Vb[lane];
            #pragma unroll
            for (int f = 0; f < EE; f++) myb = fmaf(acc[f], ws1[lane][f], myb);
        }
        float base[EE];
        #pragma unroll
        for (int o = 0; o < EE; o++) base[o] = __shfl_sync(0xffffffffu, myb, o);

        const float4* drow4 = (const float4*)(dist + (size_t)row * NNA);

        #pragma unroll
        for (int it = 0; it < 2; it++) {
            float4 x4 = __ldg(&drow4[lane + 32 * it]);
            float xs[4] = {x4.x, x4.y, x4.z, x4.w};
            #pragma unroll
            for (int q = 0; q < 4; q++) {
                float x = xs[q];
                int idx = (int)(x * INV_H);
                idx = (idx > NIV - 1) ? (NIV - 1) : idx;
                float tl = x - (float)idx * H_STEP;
                const float4* cp = &tab[idx * EE];
                #pragma unroll
                for (int o = 0; o < EE; o++) {
                    float4 c = cp[o];
                    float m = fmaf(tl, fmaf(tl, fmaf(tl, c.w, c.z), c.y), base[o] + c.x);
                    acc[o] += tanh_fast(m);
                }
            }
        }
    }

    // deterministic warp butterfly reduce
    #pragma unroll
    for (int o = 0; o < EE; o++) {
        float v = acc[o];
        #pragma unroll
        for (int off = 16; off > 0; off >>= 1)
            v += __shfl_xor_sync(0xffffffffu, v, off);
        acc[o] = v;
    }

    if (lane == 0) {
        float s = 0.0f;
        if (mk != 0.0f) {
            // cfeat entered acc identically in all 32 lanes: c = acc - 31*cfeat
            #pragma unroll
            for (int o = 0; o < EE; o++) {
                float cf = emb[zi * EE + o];
                float c  = acc[o] - 31.0f * cf;
                s = fmaf(us[o], tanh_fast(c), s);
            }
        }
        g_rowsum[row] = s;
    }
}

// ---------------- kernel 3: final deterministic reduce ----------------
__global__ void k_final(float* __restrict__ out) {
    __shared__ float red[NNA];
    int b = blockIdx.x, t = threadIdx.x;
    red[t] = g_rowsum[b * NNA + t];
    __syncthreads();
    #pragma unroll
    for (int s = NNA / 2; s > 0; s >>= 1) {
        if (t < s) red[t] += red[t + s];
        __syncthreads();
    }
    if (t == 0) out[b] = red[0] + (float)NNA * g_v;
}

// ---------------- launcher (4 launches: ncu -s 5 lands on k_main) ----------------
extern "C" void kernel_launch(void* const* d_in, const int* in_sizes, int n_in,
                              void* d_out, int out_size) {
    const int*   z    = (const int*)  d_in[0];
    const float* dist = (const float*)d_in[1];
    const float* emb  = (const float*)d_in[2];
    const float* Vw   = (const float*)d_in[3];
    const float* Vb   = (const float*)d_in[4];
    const float* W1   = (const float*)d_in[5];
    const float* b1   = (const float*)d_in[6];
    const float* W2   = (const float*)d_in[7];
    const float* b2   = (const float*)d_in[8];
    float* out = (float*)d_out;

    k_build <<<(NIV * EE + 127) / 128, 128>>>(Vw);
    k_main  <<<BB * NNA / 8, 256>>>(z, dist, emb, Vw, Vb, W1, W2);
    k_vconst<<<1, 32>>>(W2, b1, b2);
    k_final <<<BB, NNA>>>(out);
}

// round 8
// speedup vs baseline: 1.2293x; 1.2293x over previous
#include <cuda_runtime.h>
#include <cstdint>

#define BB 64
#define NNA 256
#define EE 20
#define DD 25
#define VW_COLS 45          // ATOMEMB + DFEAT
#define NIV 128             // table intervals over [0,5)
#define H_STEP 0.0390625f   // 5/128, exact in fp32
#define INV_H 25.6f

// scratch (__device__ globals per allocation-free rule)
__device__ float4 g_tab[NIV * EE];   // Hermite coeffs of E_o(x)=exp(2*t_o(x))
__device__ float  g_rowsum[BB * NNA];
__device__ float  g_v;               // b2 + W2.b1
__device__ float  g_us[EE];          // u = W2 @ W1

// ---------------- fast math ----------------
__device__ __forceinline__ float ex2f(float x) {
    float y; asm("ex2.approx.f32 %0, %1;" : "=f"(y) : "f"(x)); return y;
}
__device__ __forceinline__ float rcpf(float x) {
    float y; asm("rcp.approx.f32 %0, %1;" : "=f"(y) : "f"(x)); return y;
}
__device__ __forceinline__ float tanh_fast(float z) {
    float t = ex2f(z * 2.8853900817779268f);   // 2*log2(e)
    return fmaf(-2.0f, rcpf(t + 1.0f), 1.0f);
}

// ---------------- kernel 0: build Hermite table of E(x)=exp(2*t_o(x)) ----------------
__global__ void k_build(const float* __restrict__ Vw) {
    int t = blockIdx.x * blockDim.x + threadIdx.x;
    if (t >= NIV * EE) return;
    int o = t % EE, iv = t / EE;
    double h  = 5.0 / 128.0;
    double x0 = iv * h, x1 = x0 + h;

    double f0 = 0, d0 = 0, f1 = 0, d1 = 0;
    #pragma unroll
    for (int d = 0; d < DD; d++) {
        double w  = (double)Vw[o * VW_COLS + 20 + d];
        double u0 = x0 - 0.2 * d;
        double g0 = exp(-2.0 * u0 * u0);
        f0 += w * g0;  d0 += w * (-4.0 * u0) * g0;
        double u1 = x1 - 0.2 * d;
        double g1 = exp(-2.0 * u1 * u1);
        f1 += w * g1;  d1 += w * (-4.0 * u1) * g1;
    }
    double E0 = exp(2.0 * f0), E1 = exp(2.0 * f1);
    double D0 = 2.0 * d0 * E0, D1 = 2.0 * d1 * E1;
    double c2 = (3.0 * (E1 - E0) - (2.0 * D0 + D1) * h) / (h * h);
    double c3 = (2.0 * (E0 - E1) + (D0 + D1) * h) / (h * h * h);
    g_tab[iv * EE + o] = make_float4((float)E0, (float)D0, (float)c2, (float)c3);
}

// ---------------- kernel 1: fold top-MLP constants ----------------
__global__ void k_vconst(const float* __restrict__ W1, const float* __restrict__ b1,
                         const float* __restrict__ W2, const float* __restrict__ b2) {
    int t = threadIdx.x;
    if (t < EE) {
        float s = 0.0f;
        #pragma unroll
        for (int k = 0; k < 10; k++) s = fmaf(W2[k], W1[k * EE + t], s);
        g_us[t] = s;
    } else if (t == EE) {
        float v = b2[0];
        #pragma unroll
        for (int k = 0; k < 10; k++) v = fmaf(W2[k], b1[k], v);
        g_v = v;
    }
}

// ---------------- kernel 2/3: main loop. One warp per row; lane = output channel ----------------
__global__ __launch_bounds__(256) void k_main(const int* __restrict__ z,
                                              const float* __restrict__ dist,
                                              const float* __restrict__ emb,
                                              const float* __restrict__ Vw,
                                              const float* __restrict__ Vb,
                                              int row0) {
    __shared__ float4 tab[NIV * EE];   // 40 KB, idx-major: tab[idx*EE + o]
    __shared__ float  ws1[EE][EE];
    __shared__ float  us_s[EE], vb_s[EE];

    int tid = threadIdx.x;
    for (int t = tid; t < NIV * EE; t += 256) tab[t] = g_tab[t];
    for (int t = tid; t < EE * EE; t += 256) {
        int o = t / EE, f = t % EE;
        ws1[o][f] = Vw[o * VW_COLS + f];
    }
    if (tid < EE) { us_s[tid] = g_us[tid]; vb_s[tid] = Vb[tid]; }
    __syncthreads();

    int warp = tid >> 5, lane = tid & 31;
    int row  = row0 + blockIdx.x * 8 + warp;

    int   zi = z[row];
    float mk = (zi != 0) ? 1.0f : 0.0f;      // uniform across warp
    int   ol = (lane < EE) ? lane : 0;       // my output channel (clamped)
    float cf = emb[zi * EE + ol] * mk;

    float s_out = 0.0f;
    if (mk != 0.0f) {
        // base_o = Vb[o] + cfeat . Vw[o,:20]; cfeat_f broadcast from lane f
        float myb = vb_s[ol];
        #pragma unroll
        for (int f = 0; f < EE; f++) {
            float cff = __shfl_sync(0xffffffffu, cf, f);
            myb = fmaf(cff, ws1[ol][f], myb);
        }
        float B = ex2f(myb * 2.8853900817779268f);   // e^{2*base_o}

        const float* drow = dist + (size_t)row * NNA;
        const float4* tabo = tab + ol;               // row base for my channel

        float R0 = 0.0f, R1 = 0.0f;
        #pragma unroll 1
        for (int ch = 0; ch < 8; ch++) {
            // each lane preprocesses its own x once per 32-j chunk
            float x  = __ldg(&drow[ch * 32 + lane]);
            float fb = x * INV_H;
            int   ib = (int)fb;  ib = (ib > NIV - 1) ? (NIV - 1) : ib;
            float tb = fmaf(-(float)ib, H_STEP, x);
            #pragma unroll 8
            for (int jj = 0; jj < 32; jj += 2) {
                int   i0 = __shfl_sync(0xffffffffu, ib, jj);
                float t0 = __shfl_sync(0xffffffffu, tb, jj);
                int   i1 = __shfl_sync(0xffffffffu, ib, jj + 1);
                float t1 = __shfl_sync(0xffffffffu, tb, jj + 1);
                float4 c0 = tabo[i0 * EE];
                float4 c1 = tabo[i1 * EE];
                float e0 = fmaf(t0, fmaf(t0, fmaf(t0, c0.w, c0.z), c0.y), c0.x);
                float e1 = fmaf(t1, fmaf(t1, fmaf(t1, c1.w, c1.z), c1.y), c1.x);
                R0 += rcpf(fmaf(B, e0, 1.0f));
                R1 += rcpf(fmaf(B, e1, 1.0f));
            }
        }
        // agg_o = sum_j tanh = 256 - 2*(R0+R1);  c_o = cfeat_o + agg_o
        float c = cf + 256.0f - 2.0f * (R0 + R1);
        s_out = (lane < EE) ? us_s[ol] * tanh_fast(c) : 0.0f;
    }

    // deterministic butterfly sum over lanes -> u . tanh(c)
    #pragma unroll
    for (int off = 16; off > 0; off >>= 1)
        s_out += __shfl_xor_sync(0xffffffffu, s_out, off);

    if (lane == 0) g_rowsum[row] = s_out;
}

// ---------------- kernel 4: final deterministic reduce ----------------
__global__ void k_final(float* __restrict__ out) {
    __shared__ float red[NNA];
    int b = blockIdx.x, t = threadIdx.x;
    red[t] = g_rowsum[b * NNA + t];
    __syncthreads();
    #pragma unroll
    for (int s = NNA / 2; s > 0; s >>= 1) {
        if (t < s) red[t] += red[t + s];
        __syncthreads();
    }
    if (t == 0) out[b] = red[0] + (float)NNA * g_v;
}

// ---------------- launcher ----------------
extern "C" void kernel_launch(void* const* d_in, const int* in_sizes, int n_in,
                              void* d_out, int out_size) {
    const int*   z    = (const int*)  d_in[0];
    const float* dist = (const float*)d_in[1];
    const float* emb  = (const float*)d_in[2];
    const float* Vw   = (const float*)d_in[3];
    const float* Vb   = (const float*)d_in[4];
    const float* W1   = (const float*)d_in[5];
    const float* b1   = (const float*)d_in[6];
    const float* W2   = (const float*)d_in[7];
    const float* b2   = (const float*)d_in[8];
    float* out = (float*)d_out;

    const int HALF_ROWS = BB * NNA / 2;               // 8192
    k_build <<<(NIV * EE + 127) / 128, 128>>>(Vw);
    k_vconst<<<1, 32>>>(W1, b1, W2, b2);
    k_main  <<<HALF_ROWS / 8, 256>>>(z, dist, emb, Vw, Vb, 0);
    k_main  <<<HALF_ROWS / 8, 256>>>(z, dist, emb, Vw, Vb, HALF_ROWS);
    k_final <<<BB, NNA>>>(out);
}